// round 1
// baseline (speedup 1.0000x reference)
#include <cuda_runtime.h>

#define T_TOKENS 4096
#define DM 512
#define NE 8
#define DF 2048
#define NPAIRS (T_TOKENS * 2)

// ---------------- device scratch (static globals; no runtime allocation) ---
__device__ int   g_counts[NE];
__device__ int   g_cursor[NE];
__device__ int   g_offsets[NE + 1];
__device__ int   g_tok_e[NPAIRS];
__device__ float g_tok_g[NPAIRS];
__device__ int   g_pair_token[NPAIRS];
__device__ int   g_slot[NPAIRS];
__device__ float g_Y1[(size_t)NPAIRS * DF];   // 64 MiB
__device__ float g_Y2[(size_t)NPAIRS * DM];   // 16 MiB

// ---------------- init ------------------------------------------------------
__global__ void init_kernel() {
    int i = threadIdx.x;
    if (i < NE) { g_counts[i] = 0; g_cursor[i] = 0; }
}

// ---------------- gating: logits -> top2 -> renormalized gates --------------
__global__ void gate_kernel(const float* __restrict__ x,
                            const float* __restrict__ Wg,
                            const float* __restrict__ bg) {
    __shared__ float sWg[DM * NE];  // 16 KB
    for (int i = threadIdx.x; i < DM * NE; i += blockDim.x) sWg[i] = Wg[i];
    __syncthreads();

    int t = blockIdx.x * blockDim.x + threadIdx.x;
    if (t >= T_TOKENS) return;
    const float* xr = x + (size_t)t * DM;

    float logit[NE];
#pragma unroll
    for (int e = 0; e < NE; e++) logit[e] = bg[e];
    for (int d = 0; d < DM; d++) {
        float xv = xr[d];
#pragma unroll
        for (int e = 0; e < NE; e++)
            logit[e] = fmaf(xv, sWg[d * NE + e], logit[e]);
    }

    // top-2 (strict > keeps lowest index on ties, matching lax.top_k)
    int i0 = 0;
#pragma unroll
    for (int e = 1; e < NE; e++) if (logit[e] > logit[i0]) i0 = e;
    int i1 = (i0 == 0) ? 1 : 0;
#pragma unroll
    for (int e = 0; e < NE; e++)
        if (e != i0 && logit[e] > logit[i1]) i1 = e;

    // renormalized top-2 gates == softmax over the two logits
    float g0 = 1.0f / (1.0f + expf(logit[i1] - logit[i0]));
    float g1 = 1.0f - g0;

    g_tok_e[t * 2 + 0] = i0;  g_tok_g[t * 2 + 0] = g0;
    g_tok_e[t * 2 + 1] = i1;  g_tok_g[t * 2 + 1] = g1;
    atomicAdd(&g_counts[i0], 1);
    atomicAdd(&g_counts[i1], 1);
}

__global__ void prefix_kernel() {
    if (threadIdx.x == 0) {
        int acc = 0;
#pragma unroll
        for (int e = 0; e < NE; e++) { g_offsets[e] = acc; acc += g_counts[e]; }
        g_offsets[NE] = acc;
    }
}

__global__ void scatter_kernel() {
    int p = blockIdx.x * blockDim.x + threadIdx.x;
    if (p >= NPAIRS) return;
    int e = g_tok_e[p];
    int pos = atomicAdd(&g_cursor[e], 1);
    int row = g_offsets[e] + pos;
    g_pair_token[row] = p >> 1;
    g_slot[p] = row;
}

// ---------------- FFN1: Y1 = relu(gather(x) @ W1[e] + b1[e]) ---------------
// 64x64 tile, BK=16, 256 threads, 4x4 micro-tile, A transposed in smem.
__global__ __launch_bounds__(256)
void ffn1_kernel(const float* __restrict__ x,
                 const float* __restrict__ W1,
                 const float* __restrict__ b1) {
    int e = blockIdx.z;
    int seg_start = g_offsets[e];
    int seg_count = g_offsets[e + 1] - seg_start;
    int m0 = blockIdx.x * 64;
    if (m0 >= seg_count) return;
    int n0 = blockIdx.y * 64;

    const float* W = W1 + (size_t)e * DM * DF;

    __shared__ __align__(16) float As[16][68];  // [k][m]
    __shared__ __align__(16) float Bs[16][68];  // [k][n]

    int tid = threadIdx.x;
    int tx = tid & 15, ty = tid >> 4;

    // A load mapping: thread -> (row am, 4 consecutive k)
    int am = tid >> 2;
    int ak = (tid & 3) * 4;
    int m_idx = m0 + am;
    int tok = g_pair_token[seg_start + (m_idx < seg_count ? m_idx : 0)];
    const float4* Ag = reinterpret_cast<const float4*>(x + (size_t)tok * DM);

    // B load mapping
    int bk = tid >> 4;
    int bn = (tid & 15) * 4;

    float acc[4][4];
#pragma unroll
    for (int i = 0; i < 4; i++)
#pragma unroll
        for (int j = 0; j < 4; j++) acc[i][j] = 0.0f;

    for (int k0 = 0; k0 < DM; k0 += 16) {
        float4 av = Ag[(k0 + ak) >> 2];
        float4 bv = *reinterpret_cast<const float4*>(W + (size_t)(k0 + bk) * DF + n0 + bn);
        __syncthreads();
        As[ak + 0][am] = av.x; As[ak + 1][am] = av.y;
        As[ak + 2][am] = av.z; As[ak + 3][am] = av.w;
        *reinterpret_cast<float4*>(&Bs[bk][bn]) = bv;
        __syncthreads();
#pragma unroll
        for (int k = 0; k < 16; k++) {
            float4 a = *reinterpret_cast<const float4*>(&As[k][ty * 4]);
            float4 b = *reinterpret_cast<const float4*>(&Bs[k][tx * 4]);
            float ar[4] = {a.x, a.y, a.z, a.w};
            float br[4] = {b.x, b.y, b.z, b.w};
#pragma unroll
            for (int i = 0; i < 4; i++)
#pragma unroll
                for (int j = 0; j < 4; j++)
                    acc[i][j] = fmaf(ar[i], br[j], acc[i][j]);
        }
    }

    float4 bb = *reinterpret_cast<const float4*>(b1 + (size_t)e * DF + n0 + tx * 4);
#pragma unroll
    for (int i = 0; i < 4; i++) {
        int m = m0 + ty * 4 + i;
        if (m < seg_count) {
            float4 o;
            o.x = fmaxf(acc[i][0] + bb.x, 0.0f);
            o.y = fmaxf(acc[i][1] + bb.y, 0.0f);
            o.z = fmaxf(acc[i][2] + bb.z, 0.0f);
            o.w = fmaxf(acc[i][3] + bb.w, 0.0f);
            *reinterpret_cast<float4*>(g_Y1 + (size_t)(seg_start + m) * DF + n0 + tx * 4) = o;
        }
    }
}

// ---------------- FFN2: Y2 = Y1 @ W2[e] + b2[e] -----------------------------
__global__ __launch_bounds__(256)
void ffn2_kernel(const float* __restrict__ W2,
                 const float* __restrict__ b2) {
    int e = blockIdx.z;
    int seg_start = g_offsets[e];
    int seg_count = g_offsets[e + 1] - seg_start;
    int m0 = blockIdx.x * 64;
    if (m0 >= seg_count) return;
    int n0 = blockIdx.y * 64;

    const float* W = W2 + (size_t)e * DF * DM;

    __shared__ __align__(16) float As[16][68];
    __shared__ __align__(16) float Bs[16][68];

    int tid = threadIdx.x;
    int tx = tid & 15, ty = tid >> 4;

    int am = tid >> 2;
    int ak = (tid & 3) * 4;
    int m_idx = m0 + am;
    int arow = seg_start + (m_idx < seg_count ? m_idx : 0);
    const float4* Ag = reinterpret_cast<const float4*>(g_Y1 + (size_t)arow * DF);

    int bk = tid >> 4;
    int bn = (tid & 15) * 4;

    float acc[4][4];
#pragma unroll
    for (int i = 0; i < 4; i++)
#pragma unroll
        for (int j = 0; j < 4; j++) acc[i][j] = 0.0f;

    for (int k0 = 0; k0 < DF; k0 += 16) {
        float4 av = Ag[(k0 + ak) >> 2];
        float4 bv = *reinterpret_cast<const float4*>(W + (size_t)(k0 + bk) * DM + n0 + bn);
        __syncthreads();
        As[ak + 0][am] = av.x; As[ak + 1][am] = av.y;
        As[ak + 2][am] = av.z; As[ak + 3][am] = av.w;
        *reinterpret_cast<float4*>(&Bs[bk][bn]) = bv;
        __syncthreads();
#pragma unroll
        for (int k = 0; k < 16; k++) {
            float4 a = *reinterpret_cast<const float4*>(&As[k][ty * 4]);
            float4 b = *reinterpret_cast<const float4*>(&Bs[k][tx * 4]);
            float ar[4] = {a.x, a.y, a.z, a.w};
            float br[4] = {b.x, b.y, b.z, b.w};
#pragma unroll
            for (int i = 0; i < 4; i++)
#pragma unroll
                for (int j = 0; j < 4; j++)
                    acc[i][j] = fmaf(ar[i], br[j], acc[i][j]);
        }
    }

    float4 bb = *reinterpret_cast<const float4*>(b2 + (size_t)e * DM + n0 + tx * 4);
#pragma unroll
    for (int i = 0; i < 4; i++) {
        int m = m0 + ty * 4 + i;
        if (m < seg_count) {
            float4 o;
            o.x = acc[i][0] + bb.x;
            o.y = acc[i][1] + bb.y;
            o.z = acc[i][2] + bb.z;
            o.w = acc[i][3] + bb.w;
            *reinterpret_cast<float4*>(g_Y2 + (size_t)(seg_start + m) * DM + n0 + tx * 4) = o;
        }
    }
}

// ---------------- combine: out[t] = g0*Y2[slot0] + g1*Y2[slot1] -------------
__global__ void combine_kernel(float* __restrict__ out) {
    int idx = blockIdx.x * blockDim.x + threadIdx.x;  // over T*DM/4
    const int vec_per_row = DM / 4;
    int t = idx / vec_per_row;
    int c = idx - t * vec_per_row;
    if (t >= T_TOKENS) return;
    int r0 = g_slot[t * 2], r1 = g_slot[t * 2 + 1];
    float g0 = g_tok_g[t * 2], g1 = g_tok_g[t * 2 + 1];
    float4 y0 = reinterpret_cast<const float4*>(g_Y2 + (size_t)r0 * DM)[c];
    float4 y1 = reinterpret_cast<const float4*>(g_Y2 + (size_t)r1 * DM)[c];
    float4 o;
    o.x = fmaf(g0, y0.x, g1 * y1.x);
    o.y = fmaf(g0, y0.y, g1 * y1.y);
    o.z = fmaf(g0, y0.z, g1 * y1.z);
    o.w = fmaf(g0, y0.w, g1 * y1.w);
    reinterpret_cast<float4*>(out)[idx] = o;
}

// ---------------- launch -----------------------------------------------------
extern "C" void kernel_launch(void* const* d_in, const int* in_sizes, int n_in,
                              void* d_out, int out_size) {
    const float* x  = (const float*)d_in[0];
    const float* Wg = (const float*)d_in[1];
    const float* bg = (const float*)d_in[2];
    const float* W1 = (const float*)d_in[3];
    const float* b1 = (const float*)d_in[4];
    const float* W2 = (const float*)d_in[5];
    const float* b2 = (const float*)d_in[6];
    float* out = (float*)d_out;

    init_kernel<<<1, 32>>>();
    gate_kernel<<<T_TOKENS / 128, 128>>>(x, Wg, bg);
    prefix_kernel<<<1, 32>>>();
    scatter_kernel<<<NPAIRS / 256, 256>>>();

    dim3 grid1(NPAIRS / 64, DF / 64, NE);   // (128, 32, 8) with early exit
    ffn1_kernel<<<grid1, 256>>>(x, W1, b1);

    dim3 grid2(NPAIRS / 64, DM / 64, NE);   // (128, 8, 8) with early exit
    ffn2_kernel<<<grid2, 256>>>(W2, b2);

    combine_kernel<<<(T_TOKENS * DM / 4 + 255) / 256, 256>>>(out);
}

// round 3
// speedup vs baseline: 2.2027x; 2.2027x over previous
#include <cuda_runtime.h>
#include <cuda_bf16.h>
#include <cstdint>

#define T_TOKENS 4096
#define DM 512
#define NE 8
#define DF 2048
#define NPAIRS (T_TOKENS * 2)

// ---------------- device scratch ------------------------------------------
__device__ int   g_counts[NE];
__device__ int   g_cursor[NE];
__device__ int   g_offsets[NE + 1];
__device__ int   g_tok_e[NPAIRS];
__device__ float g_tok_g[NPAIRS];
__device__ int   g_pair_token[NPAIRS];
__device__ int   g_slot[NPAIRS];
__device__ __nv_bfloat16 g_xg_h[(size_t)NPAIRS * DM];   // 8 MiB
__device__ __nv_bfloat16 g_xg_l[(size_t)NPAIRS * DM];   // 8 MiB
__device__ __nv_bfloat16 g_Y1h[(size_t)NPAIRS * DF];    // 32 MiB
__device__ __nv_bfloat16 g_Y1l[(size_t)NPAIRS * DF];    // 32 MiB
__device__ float g_Y2[(size_t)NPAIRS * DM];             // 16 MiB

// ---------------- helpers ----------------------------------------------------
// fp32 -> (hi,lo) bf16x2 packed as u32 (.x in low half)
__device__ __forceinline__ void split2(float x, float y, uint32_t& hi, uint32_t& lo) {
    __nv_bfloat16 hx = __float2bfloat16(x);
    __nv_bfloat16 hy = __float2bfloat16(y);
    float rx = x - __bfloat162float(hx);
    float ry = y - __bfloat162float(hy);
    __nv_bfloat16 lx = __float2bfloat16(rx);
    __nv_bfloat16 ly = __float2bfloat16(ry);
    __nv_bfloat162 h2(hx, hy), l2(lx, ly);
    hi = *reinterpret_cast<uint32_t*>(&h2);
    lo = *reinterpret_cast<uint32_t*>(&l2);
}

#define LDSM_X4(R, ADDR) \
    asm volatile("ldmatrix.sync.aligned.m8n8.x4.shared.b16 {%0,%1,%2,%3}, [%4];" \
        : "=r"((R)[0]), "=r"((R)[1]), "=r"((R)[2]), "=r"((R)[3]) : "r"(ADDR))

#define LDSM_X4T(R0, R1, R2, R3, ADDR) \
    asm volatile("ldmatrix.sync.aligned.m8n8.x4.trans.shared.b16 {%0,%1,%2,%3}, [%4];" \
        : "=r"(R0), "=r"(R1), "=r"(R2), "=r"(R3) : "r"(ADDR))

#define MMA_BF16(C, A, B) \
    asm volatile("mma.sync.aligned.m16n8k16.row.col.f32.bf16.bf16.f32 " \
        "{%0,%1,%2,%3}, {%4,%5,%6,%7}, {%8,%9}, {%0,%1,%2,%3};" \
        : "+f"((C)[0]), "+f"((C)[1]), "+f"((C)[2]), "+f"((C)[3]) \
        : "r"((A)[0]), "r"((A)[1]), "r"((A)[2]), "r"((A)[3]), \
          "r"((B)[0]), "r"((B)[1]))

// ---------------- init / gating / routing ----------------------------------
__global__ void init_kernel() {
    int i = threadIdx.x;
    if (i < NE) { g_counts[i] = 0; g_cursor[i] = 0; }
}

__global__ void gate_kernel(const float* __restrict__ x,
                            const float* __restrict__ Wg,
                            const float* __restrict__ bg) {
    __shared__ float sWg[DM * NE];
    for (int i = threadIdx.x; i < DM * NE; i += blockDim.x) sWg[i] = Wg[i];
    __syncthreads();

    int t = blockIdx.x * blockDim.x + threadIdx.x;
    if (t >= T_TOKENS) return;
    const float* xr = x + (size_t)t * DM;

    float logit[NE];
#pragma unroll
    for (int e = 0; e < NE; e++) logit[e] = bg[e];
    for (int d = 0; d < DM; d++) {
        float xv = xr[d];
#pragma unroll
        for (int e = 0; e < NE; e++)
            logit[e] = fmaf(xv, sWg[d * NE + e], logit[e]);
    }
    int i0 = 0;
#pragma unroll
    for (int e = 1; e < NE; e++) if (logit[e] > logit[i0]) i0 = e;
    int i1 = (i0 == 0) ? 1 : 0;
#pragma unroll
    for (int e = 0; e < NE; e++)
        if (e != i0 && logit[e] > logit[i1]) i1 = e;

    float g0 = 1.0f / (1.0f + expf(logit[i1] - logit[i0]));
    float g1 = 1.0f - g0;

    g_tok_e[t * 2 + 0] = i0;  g_tok_g[t * 2 + 0] = g0;
    g_tok_e[t * 2 + 1] = i1;  g_tok_g[t * 2 + 1] = g1;
    atomicAdd(&g_counts[i0], 1);
    atomicAdd(&g_counts[i1], 1);
}

__global__ void prefix_kernel() {
    if (threadIdx.x == 0) {
        int acc = 0;
#pragma unroll
        for (int e = 0; e < NE; e++) { g_offsets[e] = acc; acc += g_counts[e]; }
        g_offsets[NE] = acc;
    }
}

__global__ void scatter_kernel() {
    int p = blockIdx.x * blockDim.x + threadIdx.x;
    if (p >= NPAIRS) return;
    int e = g_tok_e[p];
    int pos = atomicAdd(&g_cursor[e], 1);
    int row = g_offsets[e] + pos;
    g_pair_token[row] = p >> 1;
    g_slot[p] = row;
}

// ---------------- gather + fp32->bf16 hi/lo split of x ----------------------
__global__ void gather_convert(const float* __restrict__ x) {
    int idx = blockIdx.x * blockDim.x + threadIdx.x;  // over NPAIRS * DM/4
    if (idx >= NPAIRS * (DM / 4)) return;
    int row = idx >> 7;          // DM/4 = 128
    int c4  = idx & 127;
    int tok = g_pair_token[row];
    float4 v = reinterpret_cast<const float4*>(x + (size_t)tok * DM)[c4];
    uint32_t h0, l0, h1, l1;
    split2(v.x, v.y, h0, l0);
    split2(v.z, v.w, h1, l1);
    size_t o = (size_t)row * DM + (size_t)c4 * 4;
    *reinterpret_cast<uint32_t*>(g_xg_h + o)     = h0;
    *reinterpret_cast<uint32_t*>(g_xg_h + o + 2) = h1;
    *reinterpret_cast<uint32_t*>(g_xg_l + o)     = l0;
    *reinterpret_cast<uint32_t*>(g_xg_l + o + 2) = l1;
}

// ---------------- split-bf16 HMMA grouped GEMM -------------------------------
// D[m,n] = sum_k A[m,k] * W[k,n].  A = Ah+Al bf16 pre-split (gathered rows).
// W fp32 converted to bf16 hi/lo while staging to smem.
// CTA tile 128x128, BK=32, 256 threads, warp tile 32x64 (4M x 2N warps).
// A smem [m][k] stride 40; B smem [k][n] stride 136 (trans ldmatrix).
template<int K_TOTAL, int N_TOTAL, int RELU_SPLIT>
__global__ __launch_bounds__(256, 1)
void moe_mma(const float* __restrict__ Wf,     // [E, K_TOTAL, N_TOTAL]
             const float* __restrict__ bias)   // [E, N_TOTAL]
{
    constexpr int NC   = K_TOTAL / 32;
    constexpr int A_SZ = 128 * 40;   // elems per A copy
    constexpr int B_SZ = 32 * 136;   // elems per B copy
    constexpr int BUF  = 2 * A_SZ + 2 * B_SZ;  // 18944 elems = 37888 B / buffer

    const int e = blockIdx.z;
    const int seg_start = g_offsets[e];
    const int seg_count = g_offsets[e + 1] - seg_start;
    const int m0 = blockIdx.x * 128;
    if (m0 >= seg_count) return;
    const int n0 = blockIdx.y * 128;

    const int tid  = threadIdx.x;
    const int lane = tid & 31;
    const int warp = tid >> 5;
    const int wm = (warp & 3) * 32;
    const int wn = (warp >> 2) * 64;

    extern __shared__ __nv_bfloat16 smraw[];
    __nv_bfloat16* sm = smraw;
    const uint32_t sbase = (uint32_t)__cvta_generic_to_shared(sm);

    const __nv_bfloat16* Ah = RELU_SPLIT ? g_xg_h : g_Y1h;
    const __nv_bfloat16* Al = RELU_SPLIT ? g_xg_l : g_Y1l;
    const float* Wp = Wf + (size_t)e * K_TOTAL * N_TOTAL + n0;

    // ---- per-thread load mappings ----
    int    a_srow[2], a_koff[2];
    size_t a_gidx[2];
#pragma unroll
    for (int it = 0; it < 2; it++) {
        int u = tid + it * 256;               // 512 int4 per A copy
        int r = m0 + (u >> 2);
        if (r >= seg_count) r = seg_count - 1;
        a_srow[it] = u >> 2;
        a_koff[it] = (u & 3) * 8;
        a_gidx[it] = (size_t)(seg_start + r) * K_TOTAL + a_koff[it];
    }
    int b_k[4], b_n[4];
#pragma unroll
    for (int it = 0; it < 4; it++) {
        int v = tid + it * 256;               // 1024 float4 per B tile
        b_k[it] = v >> 5;
        b_n[it] = (v & 31) * 4;
    }

    // ldmatrix smem element offsets (per lane)
    const uint32_t aoff = (uint32_t)((wm + (lane & 15)) * 40 + (lane >> 4) * 8);
    const uint32_t boff = (uint32_t)((((lane >> 3) & 1) * 8 + (lane & 7)) * 136
                                     + wn + (lane >> 4) * 8);

    float c[16][4];
#pragma unroll
    for (int f = 0; f < 16; f++)
#pragma unroll
        for (int q = 0; q < 4; q++) c[f][q] = 0.0f;

    int4   pa_h[2], pa_l[2];
    float4 pb[4];

#define LOAD_REGS(KC) do { \
    _Pragma("unroll") \
    for (int it = 0; it < 2; it++) { \
        pa_h[it] = *reinterpret_cast<const int4*>(Ah + a_gidx[it] + (size_t)(KC) * 32); \
        pa_l[it] = *reinterpret_cast<const int4*>(Al + a_gidx[it] + (size_t)(KC) * 32); \
    } \
    _Pragma("unroll") \
    for (int it = 0; it < 4; it++) \
        pb[it] = *reinterpret_cast<const float4*>( \
            Wp + (size_t)((KC) * 32 + b_k[it]) * N_TOTAL + b_n[it]); \
} while (0)

#define STORE_SMEM(BSEL) do { \
    __nv_bfloat16* S = sm + (BSEL) * BUF; \
    _Pragma("unroll") \
    for (int it = 0; it < 2; it++) { \
        *reinterpret_cast<int4*>(S + a_srow[it] * 40 + a_koff[it]) = pa_h[it]; \
        *reinterpret_cast<int4*>(S + A_SZ + a_srow[it] * 40 + a_koff[it]) = pa_l[it]; \
    } \
    _Pragma("unroll") \
    for (int it = 0; it < 4; it++) { \
        uint32_t h0, l0, h1, l1; \
        split2(pb[it].x, pb[it].y, h0, l0); \
        split2(pb[it].z, pb[it].w, h1, l1); \
        uint2 hh; hh.x = h0; hh.y = h1; \
        uint2 ll; ll.x = l0; ll.y = l1; \
        *reinterpret_cast<uint2*>(S + 2 * A_SZ + b_k[it] * 136 + b_n[it]) = hh; \
        *reinterpret_cast<uint2*>(S + 2 * A_SZ + B_SZ + b_k[it] * 136 + b_n[it]) = ll; \
    } \
} while (0)

#define COMPUTE(BSEL) do { \
    uint32_t base = sbase + (uint32_t)(BSEL) * (BUF * 2); \
    _Pragma("unroll") \
    for (int kt = 0; kt < 2; kt++) { \
        uint32_t ah[2][4], al[2][4]; \
        _Pragma("unroll") \
        for (int mt = 0; mt < 2; mt++) { \
            uint32_t ad = base + 2u * (aoff + (uint32_t)(mt * 640 + kt * 16)); \
            LDSM_X4(ah[mt], ad); \
            LDSM_X4(al[mt], ad + 2u * A_SZ); \
        } \
        uint32_t bh[8][2], bl[8][2]; \
        _Pragma("unroll") \
        for (int bt = 0; bt < 4; bt++) { \
            uint32_t bd = base + 2u * ((uint32_t)(2 * A_SZ) + boff \
                                       + (uint32_t)(bt * 16 + kt * 16 * 136)); \
            LDSM_X4T(bh[bt * 2][0], bh[bt * 2][1], bh[bt * 2 + 1][0], bh[bt * 2 + 1][1], bd); \
            LDSM_X4T(bl[bt * 2][0], bl[bt * 2][1], bl[bt * 2 + 1][0], bl[bt * 2 + 1][1], \
                     bd + 2u * B_SZ); \
        } \
        _Pragma("unroll") \
        for (int mt = 0; mt < 2; mt++) { \
            _Pragma("unroll") \
            for (int nt = 0; nt < 8; nt++) { \
                float* cc = c[mt * 8 + nt]; \
                MMA_BF16(cc, ah[mt], bh[nt]); \
                MMA_BF16(cc, ah[mt], bl[nt]); \
                MMA_BF16(cc, al[mt], bh[nt]); \
            } \
        } \
    } \
} while (0)

    // ---- software-pipelined mainloop ----
    LOAD_REGS(0);
    STORE_SMEM(0);
    LOAD_REGS(1);
    __syncthreads();
    for (int kc = 0; kc < NC; kc++) {
        COMPUTE(kc & 1);
        if (kc + 1 < NC) STORE_SMEM((kc + 1) & 1);
        __syncthreads();
        if (kc + 2 < NC) LOAD_REGS(kc + 2);
    }

#undef LOAD_REGS
#undef STORE_SMEM
#undef COMPUTE

    // ---- epilogue ----
    const float* bp = bias + (size_t)e * N_TOTAL + n0;
    const int rbase = m0 + wm + (lane >> 2);
#pragma unroll
    for (int mt = 0; mt < 2; mt++) {
#pragma unroll
        for (int nt = 0; nt < 8; nt++) {
            float* cc = c[mt * 8 + nt];
            int col = wn + nt * 8 + 2 * (lane & 3);
            float2 bb = *reinterpret_cast<const float2*>(bp + col);
#pragma unroll
            for (int h = 0; h < 2; h++) {
                int r = rbase + mt * 16 + h * 8;
                if (r < seg_count) {
                    float v0 = cc[h * 2 + 0] + bb.x;
                    float v1 = cc[h * 2 + 1] + bb.y;
                    size_t off = (size_t)(seg_start + r) * N_TOTAL + n0 + col;
                    if (RELU_SPLIT) {
                        v0 = fmaxf(v0, 0.0f);
                        v1 = fmaxf(v1, 0.0f);
                        uint32_t hh, ll;
                        split2(v0, v1, hh, ll);
                        *reinterpret_cast<uint32_t*>(g_Y1h + off) = hh;
                        *reinterpret_cast<uint32_t*>(g_Y1l + off) = ll;
                    } else {
                        float2 o; o.x = v0; o.y = v1;
                        *reinterpret_cast<float2*>(g_Y2 + off) = o;
                    }
                }
            }
        }
    }
}

// ---------------- combine ----------------------------------------------------
__global__ void combine_kernel(float* __restrict__ out) {
    int idx = blockIdx.x * blockDim.x + threadIdx.x;
    const int vec_per_row = DM / 4;
    int t = idx / vec_per_row;
    int c = idx - t * vec_per_row;
    if (t >= T_TOKENS) return;
    int r0 = g_slot[t * 2], r1 = g_slot[t * 2 + 1];
    float g0 = g_tok_g[t * 2], g1 = g_tok_g[t * 2 + 1];
    float4 y0 = reinterpret_cast<const float4*>(g_Y2 + (size_t)r0 * DM)[c];
    float4 y1 = reinterpret_cast<const float4*>(g_Y2 + (size_t)r1 * DM)[c];
    float4 o;
    o.x = fmaf(g0, y0.x, g1 * y1.x);
    o.y = fmaf(g0, y0.y, g1 * y1.y);
    o.z = fmaf(g0, y0.z, g1 * y1.z);
    o.w = fmaf(g0, y0.w, g1 * y1.w);
    reinterpret_cast<float4*>(out)[idx] = o;
}

// ---------------- launch ------------------------------------------------------
extern "C" void kernel_launch(void* const* d_in, const int* in_sizes, int n_in,
                              void* d_out, int out_size) {
    const float* x  = (const float*)d_in[0];
    const float* Wg = (const float*)d_in[1];
    const float* bg = (const float*)d_in[2];
    const float* W1 = (const float*)d_in[3];
    const float* b1 = (const float*)d_in[4];
    const float* W2 = (const float*)d_in[5];
    const float* b2 = (const float*)d_in[6];
    float* out = (float*)d_out;

    constexpr int SMEM = 2 * (2 * 128 * 40 + 2 * 32 * 136) * 2;  // 75776 bytes
    cudaFuncSetAttribute(moe_mma<DM, DF, 1>,
                         cudaFuncAttributeMaxDynamicSharedMemorySize, SMEM);
    cudaFuncSetAttribute(moe_mma<DF, DM, 0>,
                         cudaFuncAttributeMaxDynamicSharedMemorySize, SMEM);

    init_kernel<<<1, 32>>>();
    gate_kernel<<<T_TOKENS / 128, 128>>>(x, Wg, bg);
    prefix_kernel<<<1, 32>>>();
    scatter_kernel<<<NPAIRS / 256, 256>>>();
    gather_convert<<<(NPAIRS * (DM / 4)) / 256, 256>>>(x);

    dim3 grid1(NPAIRS / 128, DF / 128, NE);   // (64, 16, 8), dead tiles exit
    moe_mma<DM, DF, 1><<<grid1, 256, SMEM>>>(W1, b1);

    dim3 grid2(NPAIRS / 128, DM / 128, NE);   // (64, 4, 8)
    moe_mma<DF, DM, 0><<<grid2, 256, SMEM>>>(W2, b2);

    combine_kernel<<<(T_TOKENS * DM / 4 + 255) / 256, 256>>>(out);
}

// round 4
// speedup vs baseline: 2.7703x; 1.2577x over previous
#include <cuda_runtime.h>
#include <cuda_fp16.h>
#include <cstdint>

#define T_TOKENS 4096
#define DM 512
#define NE 8
#define DF 2048
#define NPAIRS (T_TOKENS * 2)

// ---------------- device scratch ------------------------------------------
__device__ int   g_counts[NE];
__device__ int   g_cursor[NE];
__device__ int   g_offsets[NE + 1];
__device__ int   g_tok_e[NPAIRS];
__device__ float g_tok_g[NPAIRS];
__device__ int   g_pair_token[NPAIRS];
__device__ int   g_slot[NPAIRS];
__device__ __half g_xg_h[(size_t)NPAIRS * DM];    // 8 MiB
__device__ __half g_xg_l[(size_t)NPAIRS * DM];    // 8 MiB
__device__ __half g_Y1h[(size_t)NPAIRS * DF];     // 32 MiB
__device__ __half g_Y1l[(size_t)NPAIRS * DF];     // 32 MiB
__device__ __half g_W1h[(size_t)NE * DM * DF];    // 16 MiB
__device__ __half g_W2h[(size_t)NE * DF * DM];    // 16 MiB
__device__ float  g_Y2[(size_t)NPAIRS * DM];      // 16 MiB

// ---------------- helpers ----------------------------------------------------
// fp32 pair -> (hi,lo) fp16x2 packed as u32 (.x in low half)
__device__ __forceinline__ void split2h(float x, float y, uint32_t& hi, uint32_t& lo) {
    __half hx = __float2half_rn(x);
    __half hy = __float2half_rn(y);
    float rx = x - __half2float(hx);
    float ry = y - __half2float(hy);
    __half2 h2 = __halves2half2(hx, hy);
    __half2 l2 = __halves2half2(__float2half_rn(rx), __float2half_rn(ry));
    hi = *reinterpret_cast<uint32_t*>(&h2);
    lo = *reinterpret_cast<uint32_t*>(&l2);
}

#define LDSM_X4(R, ADDR) \
    asm volatile("ldmatrix.sync.aligned.m8n8.x4.shared.b16 {%0,%1,%2,%3}, [%4];" \
        : "=r"((R)[0]), "=r"((R)[1]), "=r"((R)[2]), "=r"((R)[3]) : "r"(ADDR))

#define LDSM_X4T(R0, R1, R2, R3, ADDR) \
    asm volatile("ldmatrix.sync.aligned.m8n8.x4.trans.shared.b16 {%0,%1,%2,%3}, [%4];" \
        : "=r"(R0), "=r"(R1), "=r"(R2), "=r"(R3) : "r"(ADDR))

#define MMA_F16(C, A, B) \
    asm volatile("mma.sync.aligned.m16n8k16.row.col.f32.f16.f16.f32 " \
        "{%0,%1,%2,%3}, {%4,%5,%6,%7}, {%8,%9}, {%0,%1,%2,%3};" \
        : "+f"((C)[0]), "+f"((C)[1]), "+f"((C)[2]), "+f"((C)[3]) \
        : "r"((A)[0]), "r"((A)[1]), "r"((A)[2]), "r"((A)[3]), \
          "r"((B)[0]), "r"((B)[1]))

#define CP16(DST, SRC) \
    asm volatile("cp.async.cg.shared.global [%0], [%1], 16;" \
        :: "r"(DST), "l"(SRC))
#define CP_COMMIT() asm volatile("cp.async.commit_group;")
#define CP_WAIT(N)  asm volatile("cp.async.wait_group %0;" :: "n"(N))

// ---------------- init / gating / routing ----------------------------------
__global__ void init_kernel() {
    int i = threadIdx.x;
    if (i < NE) { g_counts[i] = 0; g_cursor[i] = 0; }
}

__global__ void gate_kernel(const float* __restrict__ x,
                            const float* __restrict__ Wg,
                            const float* __restrict__ bg) {
    __shared__ float sWg[DM * NE];
    for (int i = threadIdx.x; i < DM * NE; i += blockDim.x) sWg[i] = Wg[i];
    __syncthreads();

    int t = blockIdx.x * blockDim.x + threadIdx.x;
    if (t >= T_TOKENS) return;
    const float* xr = x + (size_t)t * DM;

    float logit[NE];
#pragma unroll
    for (int e = 0; e < NE; e++) logit[e] = bg[e];
    for (int d = 0; d < DM; d++) {
        float xv = xr[d];
#pragma unroll
        for (int e = 0; e < NE; e++)
            logit[e] = fmaf(xv, sWg[d * NE + e], logit[e]);
    }
    int i0 = 0;
#pragma unroll
    for (int e = 1; e < NE; e++) if (logit[e] > logit[i0]) i0 = e;
    int i1 = (i0 == 0) ? 1 : 0;
#pragma unroll
    for (int e = 0; e < NE; e++)
        if (e != i0 && logit[e] > logit[i1]) i1 = e;

    float g0 = 1.0f / (1.0f + expf(logit[i1] - logit[i0]));
    float g1 = 1.0f - g0;

    g_tok_e[t * 2 + 0] = i0;  g_tok_g[t * 2 + 0] = g0;
    g_tok_e[t * 2 + 1] = i1;  g_tok_g[t * 2 + 1] = g1;
    atomicAdd(&g_counts[i0], 1);
    atomicAdd(&g_counts[i1], 1);
}

__global__ void prefix_kernel() {
    if (threadIdx.x == 0) {
        int acc = 0;
#pragma unroll
        for (int e = 0; e < NE; e++) { g_offsets[e] = acc; acc += g_counts[e]; }
        g_offsets[NE] = acc;
    }
}

__global__ void scatter_kernel() {
    int p = blockIdx.x * blockDim.x + threadIdx.x;
    if (p >= NPAIRS) return;
    int e = g_tok_e[p];
    int pos = atomicAdd(&g_cursor[e], 1);
    int row = g_offsets[e] + pos;
    g_pair_token[row] = p >> 1;
    g_slot[p] = row;
}

// ---------------- gather + fp32->fp16 hi/lo split of x ----------------------
__global__ void gather_convert(const float* __restrict__ x) {
    int idx = blockIdx.x * blockDim.x + threadIdx.x;  // over NPAIRS * DM/4
    if (idx >= NPAIRS * (DM / 4)) return;
    int row = idx >> 7;          // DM/4 = 128
    int c4  = idx & 127;
    int tok = g_pair_token[row];
    float4 v = reinterpret_cast<const float4*>(x + (size_t)tok * DM)[c4];
    uint32_t h0, l0, h1, l1;
    split2h(v.x, v.y, h0, l0);
    split2h(v.z, v.w, h1, l1);
    size_t o = (size_t)row * DM + (size_t)c4 * 4;
    uint2 hh; hh.x = h0; hh.y = h1;
    uint2 ll; ll.x = l0; ll.y = l1;
    *reinterpret_cast<uint2*>(g_xg_h + o) = hh;
    *reinterpret_cast<uint2*>(g_xg_l + o) = ll;
}

// ---------------- one-time W -> fp16 conversion ------------------------------
template<int WHICH>
__global__ void convert_w(const float* __restrict__ W) {
    __half* dst = WHICH ? g_W2h : g_W1h;
    int idx = blockIdx.x * blockDim.x + threadIdx.x;  // over elems/4
    float4 v = reinterpret_cast<const float4*>(W)[idx];
    __half2 a = __floats2half2_rn(v.x, v.y);
    __half2 b = __floats2half2_rn(v.z, v.w);
    uint2 o;
    o.x = *reinterpret_cast<uint32_t*>(&a);
    o.y = *reinterpret_cast<uint32_t*>(&b);
    *reinterpret_cast<uint2*>(dst + (size_t)idx * 4) = o;
}

// ---------------- split-fp16 HMMA grouped GEMM -------------------------------
// D = (A_hi + A_lo) @ B_hi.  A pre-split fp16 (gathered / Y1), B = W fp16.
// CTA tile 128x128, BK=32, 256 threads, warp tile 32x64, cp.async 3-stage.
template<int K_TOTAL, int N_TOTAL, int RELU_SPLIT>
__global__ __launch_bounds__(256, 1)
void moe_mma(const float* __restrict__ bias)   // [E, N_TOTAL]
{
    constexpr int NC   = K_TOTAL / 32;
    constexpr int A_SZ = 128 * 40;               // elems per A copy
    constexpr int B_SZ = 32 * 136;               // elems (hi only)
    constexpr int BUF  = 2 * A_SZ + B_SZ;        // 14592 elems = 29184 B

    const int e = blockIdx.z;
    const int seg_start = g_offsets[e];
    const int seg_count = g_offsets[e + 1] - seg_start;
    const int m0 = blockIdx.x * 128;
    if (m0 >= seg_count) return;
    const int n0 = blockIdx.y * 128;

    const int tid  = threadIdx.x;
    const int lane = tid & 31;
    const int warp = tid >> 5;
    const int wm = (warp & 3) * 32;
    const int wn = (warp >> 2) * 64;

    extern __shared__ __half smraw[];
    const uint32_t sbase = (uint32_t)__cvta_generic_to_shared(smraw);

    const __half* Ah = RELU_SPLIT ? g_xg_h : g_Y1h;
    const __half* Al = RELU_SPLIT ? g_xg_l : g_Y1l;
    const __half* Bh = RELU_SPLIT ? g_W1h  : g_W2h;
    const __half* Bp = Bh + (size_t)e * K_TOTAL * N_TOTAL + n0;

    // ---- per-thread cp.async mappings ----
    uint32_t a_soff[2];
    size_t   a_gidx[2];
#pragma unroll
    for (int it = 0; it < 2; it++) {
        int u = tid + it * 256;                  // 512 int4 per A copy
        int r = m0 + (u >> 2);
        if (r >= seg_count) r = seg_count - 1;
        a_soff[it] = (uint32_t)((u >> 2) * 40 + (u & 3) * 8) * 2;
        a_gidx[it] = (size_t)(seg_start + r) * K_TOTAL + (u & 3) * 8;
    }
    uint32_t b_soff[2];
    size_t   b_gidx[2];
#pragma unroll
    for (int it = 0; it < 2; it++) {
        int v = tid + it * 256;                  // 512 int4 for B hi
        int bk = v >> 4, bn = (v & 15) * 8;
        b_soff[it] = (uint32_t)(2 * A_SZ + bk * 136 + bn) * 2;
        b_gidx[it] = (size_t)bk * N_TOTAL + bn;
    }

    const uint32_t aoff = (uint32_t)((wm + (lane & 15)) * 40 + (lane >> 4) * 8);
    const uint32_t boff = (uint32_t)((((lane >> 3) & 1) * 8 + (lane & 7)) * 136
                                     + wn + (lane >> 4) * 8);

    float c[16][4];
#pragma unroll
    for (int f = 0; f < 16; f++)
#pragma unroll
        for (int q = 0; q < 4; q++) c[f][q] = 0.0f;

#define ISSUE(KC, BS) do { \
    uint32_t base_ = sbase + (uint32_t)(BS) * (BUF * 2); \
    _Pragma("unroll") \
    for (int it = 0; it < 2; it++) { \
        CP16(base_ + a_soff[it], Ah + a_gidx[it] + (size_t)(KC) * 32); \
        CP16(base_ + a_soff[it] + A_SZ * 2, Al + a_gidx[it] + (size_t)(KC) * 32); \
    } \
    _Pragma("unroll") \
    for (int it = 0; it < 2; it++) \
        CP16(base_ + b_soff[it], Bp + b_gidx[it] + (size_t)(KC) * 32 * N_TOTAL); \
} while (0)

#define COMPUTE(BS) do { \
    uint32_t base_ = sbase + (uint32_t)(BS) * (BUF * 2); \
    _Pragma("unroll") \
    for (int kt = 0; kt < 2; kt++) { \
        uint32_t ah[2][4], al[2][4]; \
        _Pragma("unroll") \
        for (int mt = 0; mt < 2; mt++) { \
            uint32_t ad = base_ + 2u * (aoff + (uint32_t)(mt * 640 + kt * 16)); \
            LDSM_X4(ah[mt], ad); \
            LDSM_X4(al[mt], ad + 2u * A_SZ); \
        } \
        uint32_t bh[8][2]; \
        _Pragma("unroll") \
        for (int bt = 0; bt < 4; bt++) { \
            uint32_t bd = base_ + 2u * ((uint32_t)(2 * A_SZ) + boff \
                                        + (uint32_t)(bt * 16 + kt * 16 * 136)); \
            LDSM_X4T(bh[bt * 2][0], bh[bt * 2][1], bh[bt * 2 + 1][0], bh[bt * 2 + 1][1], bd); \
        } \
        _Pragma("unroll") \
        for (int mt = 0; mt < 2; mt++) { \
            _Pragma("unroll") \
            for (int nt = 0; nt < 8; nt++) { \
                float* cc = c[mt * 8 + nt]; \
                MMA_F16(cc, ah[mt], bh[nt]); \
                MMA_F16(cc, al[mt], bh[nt]); \
            } \
        } \
    } \
} while (0)

    // ---- 3-stage cp.async pipeline ----
    ISSUE(0, 0); CP_COMMIT();
    ISSUE(1, 1); CP_COMMIT();
    int cur = 0, pre = 2;
    for (int kc = 0; kc < NC; kc++) {
        if (kc + 1 < NC) { CP_WAIT(1); } else { CP_WAIT(0); }
        __syncthreads();
        if (kc + 2 < NC) { ISSUE(kc + 2, pre); CP_COMMIT(); }
        COMPUTE(cur);
        cur = (cur == 2) ? 0 : cur + 1;
        pre = (pre == 2) ? 0 : pre + 1;
    }

#undef ISSUE
#undef COMPUTE

    // ---- epilogue ----
    const float* bp = bias + (size_t)e * N_TOTAL + n0;
    const int rbase = m0 + wm + (lane >> 2);
#pragma unroll
    for (int mt = 0; mt < 2; mt++) {
#pragma unroll
        for (int nt = 0; nt < 8; nt++) {
            float* cc = c[mt * 8 + nt];
            int col = wn + nt * 8 + 2 * (lane & 3);
            float2 bb = *reinterpret_cast<const float2*>(bp + col);
#pragma unroll
            for (int h = 0; h < 2; h++) {
                int r = rbase + mt * 16 + h * 8;
                if (r < seg_count) {
                    float v0 = cc[h * 2 + 0] + bb.x;
                    float v1 = cc[h * 2 + 1] + bb.y;
                    size_t off = (size_t)(seg_start + r) * N_TOTAL + n0 + col;
                    if (RELU_SPLIT) {
                        v0 = fmaxf(v0, 0.0f);
                        v1 = fmaxf(v1, 0.0f);
                        uint32_t hh, ll;
                        split2h(v0, v1, hh, ll);
                        *reinterpret_cast<uint32_t*>(g_Y1h + off) = hh;
                        *reinterpret_cast<uint32_t*>(g_Y1l + off) = ll;
                    } else {
                        float2 o; o.x = v0; o.y = v1;
                        *reinterpret_cast<float2*>(g_Y2 + off) = o;
                    }
                }
            }
        }
    }
}

// ---------------- combine ----------------------------------------------------
__global__ void combine_kernel(float* __restrict__ out) {
    int idx = blockIdx.x * blockDim.x + threadIdx.x;
    const int vec_per_row = DM / 4;
    int t = idx / vec_per_row;
    int c = idx - t * vec_per_row;
    if (t >= T_TOKENS) return;
    int r0 = g_slot[t * 2], r1 = g_slot[t * 2 + 1];
    float g0 = g_tok_g[t * 2], g1 = g_tok_g[t * 2 + 1];
    float4 y0 = reinterpret_cast<const float4*>(g_Y2 + (size_t)r0 * DM)[c];
    float4 y1 = reinterpret_cast<const float4*>(g_Y2 + (size_t)r1 * DM)[c];
    float4 o;
    o.x = fmaf(g0, y0.x, g1 * y1.x);
    o.y = fmaf(g0, y0.y, g1 * y1.y);
    o.z = fmaf(g0, y0.z, g1 * y1.z);
    o.w = fmaf(g0, y0.w, g1 * y1.w);
    reinterpret_cast<float4*>(out)[idx] = o;
}

// ---------------- launch ------------------------------------------------------
extern "C" void kernel_launch(void* const* d_in, const int* in_sizes, int n_in,
                              void* d_out, int out_size) {
    const float* x  = (const float*)d_in[0];
    const float* Wg = (const float*)d_in[1];
    const float* bg = (const float*)d_in[2];
    const float* W1 = (const float*)d_in[3];
    const float* b1 = (const float*)d_in[4];
    const float* W2 = (const float*)d_in[5];
    const float* b2 = (const float*)d_in[6];
    float* out = (float*)d_out;

    constexpr int BUF_BYTES = (2 * 128 * 40 + 32 * 136) * 2;  // 29184
    constexpr int SMEM = 3 * BUF_BYTES;                       // 87552
    cudaFuncSetAttribute(moe_mma<DM, DF, 1>,
                         cudaFuncAttributeMaxDynamicSharedMemorySize, SMEM);
    cudaFuncSetAttribute(moe_mma<DF, DM, 0>,
                         cudaFuncAttributeMaxDynamicSharedMemorySize, SMEM);

    init_kernel<<<1, 32>>>();
    gate_kernel<<<T_TOKENS / 128, 128>>>(x, Wg, bg);
    prefix_kernel<<<1, 32>>>();
    scatter_kernel<<<NPAIRS / 256, 256>>>();
    gather_convert<<<(NPAIRS * (DM / 4)) / 256, 256>>>(x);
    convert_w<0><<<(NE * DM * DF / 4) / 256, 256>>>(W1);
    convert_w<1><<<(NE * DF * DM / 4) / 256, 256>>>(W2);

    dim3 grid1(NPAIRS / 128, DF / 128, NE);   // (64, 16, 8), dead tiles exit
    moe_mma<DM, DF, 1><<<grid1, 256, SMEM>>>(b1);

    dim3 grid2(NPAIRS / 128, DM / 128, NE);   // (64, 4, 8)
    moe_mma<DF, DM, 0><<<grid2, 256, SMEM>>>(b2);

    combine_kernel<<<(T_TOKENS * DM / 4 + 255) / 256, 256>>>(out);
}

// round 5
// speedup vs baseline: 4.4892x; 1.6205x over previous
#include <cuda_runtime.h>
#include <cuda_fp16.h>
#include <cstdint>

#define T_TOKENS 4096
#define DM 512
#define NE 8
#define DF 2048
#define NPAIRS (T_TOKENS * 2)

// ---------------- device scratch ------------------------------------------
__device__ int   g_counts[NE];
__device__ int   g_cursor[NE];
__device__ int   g_offsets[NE + 1];
__device__ int   g_tok_e[NPAIRS];
__device__ float g_tok_g[NPAIRS];
__device__ int   g_pair_token[NPAIRS];
__device__ int   g_slot[NPAIRS];
__device__ __half g_xg[(size_t)NPAIRS * DM];      // 8 MiB
__device__ __half g_Y1[(size_t)NPAIRS * DF];      // 32 MiB
__device__ __half g_W1h[(size_t)NE * DM * DF];    // 16 MiB
__device__ __half g_W2h[(size_t)NE * DF * DM];    // 16 MiB
__device__ float  g_Y2[(size_t)NPAIRS * DM];      // 16 MiB

// ---------------- helpers ----------------------------------------------------
#define LDSM_X4(R, ADDR) \
    asm volatile("ldmatrix.sync.aligned.m8n8.x4.shared.b16 {%0,%1,%2,%3}, [%4];" \
        : "=r"((R)[0]), "=r"((R)[1]), "=r"((R)[2]), "=r"((R)[3]) : "r"(ADDR))

#define LDSM_X4T(R0, R1, R2, R3, ADDR) \
    asm volatile("ldmatrix.sync.aligned.m8n8.x4.trans.shared.b16 {%0,%1,%2,%3}, [%4];" \
        : "=r"(R0), "=r"(R1), "=r"(R2), "=r"(R3) : "r"(ADDR))

#define MMA_F16(C, A, B) \
    asm volatile("mma.sync.aligned.m16n8k16.row.col.f32.f16.f16.f32 " \
        "{%0,%1,%2,%3}, {%4,%5,%6,%7}, {%8,%9}, {%0,%1,%2,%3};" \
        : "+f"((C)[0]), "+f"((C)[1]), "+f"((C)[2]), "+f"((C)[3]) \
        : "r"((A)[0]), "r"((A)[1]), "r"((A)[2]), "r"((A)[3]), \
          "r"((B)[0]), "r"((B)[1]))

#define CP16(DST, SRC) \
    asm volatile("cp.async.cg.shared.global [%0], [%1], 16;" \
        :: "r"(DST), "l"(SRC))
#define CP_COMMIT() asm volatile("cp.async.commit_group;")
#define CP_WAIT(N)  asm volatile("cp.async.wait_group %0;" :: "n"(N))

// ---------------- init / gating / routing ----------------------------------
__global__ void init_kernel() {
    int i = threadIdx.x;
    if (i < NE) { g_counts[i] = 0; g_cursor[i] = 0; }
}

__global__ void gate_kernel(const float* __restrict__ x,
                            const float* __restrict__ Wg,
                            const float* __restrict__ bg) {
    __shared__ float sWg[DM * NE];
    for (int i = threadIdx.x; i < DM * NE; i += blockDim.x) sWg[i] = Wg[i];
    __syncthreads();

    int t = blockIdx.x * blockDim.x + threadIdx.x;
    if (t >= T_TOKENS) return;
    const float* xr = x + (size_t)t * DM;

    float logit[NE];
#pragma unroll
    for (int e = 0; e < NE; e++) logit[e] = bg[e];
    for (int d = 0; d < DM; d++) {
        float xv = xr[d];
#pragma unroll
        for (int e = 0; e < NE; e++)
            logit[e] = fmaf(xv, sWg[d * NE + e], logit[e]);
    }
    int i0 = 0;
#pragma unroll
    for (int e = 1; e < NE; e++) if (logit[e] > logit[i0]) i0 = e;
    int i1 = (i0 == 0) ? 1 : 0;
#pragma unroll
    for (int e = 0; e < NE; e++)
        if (e != i0 && logit[e] > logit[i1]) i1 = e;

    float g0 = 1.0f / (1.0f + expf(logit[i1] - logit[i0]));
    float g1 = 1.0f - g0;

    g_tok_e[t * 2 + 0] = i0;  g_tok_g[t * 2 + 0] = g0;
    g_tok_e[t * 2 + 1] = i1;  g_tok_g[t * 2 + 1] = g1;
    atomicAdd(&g_counts[i0], 1);
    atomicAdd(&g_counts[i1], 1);
}

__global__ void prefix_kernel() {
    if (threadIdx.x == 0) {
        int acc = 0;
#pragma unroll
        for (int e = 0; e < NE; e++) { g_offsets[e] = acc; acc += g_counts[e]; }
        g_offsets[NE] = acc;
    }
}

__global__ void scatter_kernel() {
    int p = blockIdx.x * blockDim.x + threadIdx.x;
    if (p >= NPAIRS) return;
    int e = g_tok_e[p];
    int pos = atomicAdd(&g_cursor[e], 1);
    int row = g_offsets[e] + pos;
    g_pair_token[row] = p >> 1;
    g_slot[p] = row;
}

// ---------------- gather x -> fp16 ------------------------------------------
__global__ void gather_convert(const float* __restrict__ x) {
    int idx = blockIdx.x * blockDim.x + threadIdx.x;  // over NPAIRS * DM/4
    if (idx >= NPAIRS * (DM / 4)) return;
    int row = idx >> 7;          // DM/4 = 128
    int c4  = idx & 127;
    int tok = g_pair_token[row];
    float4 v = reinterpret_cast<const float4*>(x + (size_t)tok * DM)[c4];
    __half2 a = __floats2half2_rn(v.x, v.y);
    __half2 b = __floats2half2_rn(v.z, v.w);
    uint2 o;
    o.x = *reinterpret_cast<uint32_t*>(&a);
    o.y = *reinterpret_cast<uint32_t*>(&b);
    *reinterpret_cast<uint2*>(g_xg + (size_t)row * DM + (size_t)c4 * 4) = o;
}

// ---------------- one-time W -> fp16 conversion ------------------------------
template<int WHICH>
__global__ void convert_w(const float* __restrict__ W) {
    __half* dst = WHICH ? g_W2h : g_W1h;
    int idx = blockIdx.x * blockDim.x + threadIdx.x;  // over elems/4
    float4 v = reinterpret_cast<const float4*>(W)[idx];
    __half2 a = __floats2half2_rn(v.x, v.y);
    __half2 b = __floats2half2_rn(v.z, v.w);
    uint2 o;
    o.x = *reinterpret_cast<uint32_t*>(&a);
    o.y = *reinterpret_cast<uint32_t*>(&b);
    *reinterpret_cast<uint2*>(dst + (size_t)idx * 4) = o;
}

// ---------------- fp16 HMMA grouped GEMM -------------------------------------
// D = A @ B.  A fp16 (gathered x / Y1), B = W fp16 (pre-converted).
// CTA tile 128x128, BK=32, 256 threads, warp tile 32x64, cp.async 3-stage.
// 2 CTAs/SM (56.8 KB smem, <=128 regs).
template<int K_TOTAL, int N_TOTAL, int RELU_OUT>
__global__ __launch_bounds__(256, 2)
void moe_mma(const float* __restrict__ bias)   // [E, N_TOTAL]
{
    constexpr int NC   = K_TOTAL / 32;
    constexpr int A_SZ = 128 * 40;               // elems
    constexpr int B_SZ = 32 * 136;               // elems
    constexpr int BUF  = A_SZ + B_SZ;            // 9472 elems = 18944 B

    const int e = blockIdx.z;
    const int seg_start = g_offsets[e];
    const int seg_count = g_offsets[e + 1] - seg_start;
    const int m0 = blockIdx.x * 128;
    if (m0 >= seg_count) return;
    const int n0 = blockIdx.y * 128;

    const int tid  = threadIdx.x;
    const int lane = tid & 31;
    const int warp = tid >> 5;
    const int wm = (warp & 3) * 32;
    const int wn = (warp >> 2) * 64;

    extern __shared__ __half smraw[];
    const uint32_t sbase = (uint32_t)__cvta_generic_to_shared(smraw);

    const __half* Ap = RELU_OUT ? g_xg : g_Y1;
    const __half* Bp = (RELU_OUT ? g_W1h : g_W2h)
                       + (size_t)e * K_TOTAL * N_TOTAL + n0;

    // ---- per-thread cp.async mappings ----
    uint32_t a_soff[2];
    size_t   a_gidx[2];
#pragma unroll
    for (int it = 0; it < 2; it++) {
        int u = tid + it * 256;                  // 512 int4 per A tile
        int r = m0 + (u >> 2);
        if (r >= seg_count) r = seg_count - 1;
        a_soff[it] = (uint32_t)((u >> 2) * 40 + (u & 3) * 8) * 2;
        a_gidx[it] = (size_t)(seg_start + r) * K_TOTAL + (u & 3) * 8;
    }
    uint32_t b_soff[2];
    size_t   b_gidx[2];
#pragma unroll
    for (int it = 0; it < 2; it++) {
        int v = tid + it * 256;                  // 512 int4 for B
        int bk = v >> 4, bn = (v & 15) * 8;
        b_soff[it] = (uint32_t)(A_SZ + bk * 136 + bn) * 2;
        b_gidx[it] = (size_t)bk * N_TOTAL + bn;
    }

    const uint32_t aoff = (uint32_t)((wm + (lane & 15)) * 40 + (lane >> 4) * 8);
    const uint32_t boff = (uint32_t)((((lane >> 3) & 1) * 8 + (lane & 7)) * 136
                                     + wn + (lane >> 4) * 8);

    float c[16][4];
#pragma unroll
    for (int f = 0; f < 16; f++)
#pragma unroll
        for (int q = 0; q < 4; q++) c[f][q] = 0.0f;

#define ISSUE(KC, BS) do { \
    uint32_t base_ = sbase + (uint32_t)(BS) * (BUF * 2); \
    _Pragma("unroll") \
    for (int it = 0; it < 2; it++) \
        CP16(base_ + a_soff[it], Ap + a_gidx[it] + (size_t)(KC) * 32); \
    _Pragma("unroll") \
    for (int it = 0; it < 2; it++) \
        CP16(base_ + b_soff[it], Bp + b_gidx[it] + (size_t)(KC) * 32 * N_TOTAL); \
} while (0)

#define COMPUTE(BS) do { \
    uint32_t base_ = sbase + (uint32_t)(BS) * (BUF * 2); \
    _Pragma("unroll") \
    for (int kt = 0; kt < 2; kt++) { \
        uint32_t ah[2][4]; \
        _Pragma("unroll") \
        for (int mt = 0; mt < 2; mt++) { \
            uint32_t ad = base_ + 2u * (aoff + (uint32_t)(mt * 640 + kt * 16)); \
            LDSM_X4(ah[mt], ad); \
        } \
        uint32_t bh[8][2]; \
        _Pragma("unroll") \
        for (int bt = 0; bt < 4; bt++) { \
            uint32_t bd = base_ + 2u * ((uint32_t)A_SZ + boff \
                                        + (uint32_t)(bt * 16 + kt * 16 * 136)); \
            LDSM_X4T(bh[bt * 2][0], bh[bt * 2][1], bh[bt * 2 + 1][0], bh[bt * 2 + 1][1], bd); \
        } \
        _Pragma("unroll") \
        for (int mt = 0; mt < 2; mt++) { \
            _Pragma("unroll") \
            for (int nt = 0; nt < 8; nt++) \
                MMA_F16(c[mt * 8 + nt], ah[mt], bh[nt]); \
        } \
    } \
} while (0)

    // ---- 3-stage cp.async pipeline ----
    ISSUE(0, 0); CP_COMMIT();
    ISSUE(1, 1); CP_COMMIT();
    int cur = 0, pre = 2;
    for (int kc = 0; kc < NC; kc++) {
        if (kc + 1 < NC) { CP_WAIT(1); } else { CP_WAIT(0); }
        __syncthreads();
        if (kc + 2 < NC) { ISSUE(kc + 2, pre); CP_COMMIT(); }
        COMPUTE(cur);
        cur = (cur == 2) ? 0 : cur + 1;
        pre = (pre == 2) ? 0 : pre + 1;
    }

#undef ISSUE
#undef COMPUTE

    // ---- epilogue ----
    const float* bp = bias + (size_t)e * N_TOTAL + n0;
    const int rbase = m0 + wm + (lane >> 2);
#pragma unroll
    for (int mt = 0; mt < 2; mt++) {
#pragma unroll
        for (int nt = 0; nt < 8; nt++) {
            float* cc = c[mt * 8 + nt];
            int col = wn + nt * 8 + 2 * (lane & 3);
            float2 bb = *reinterpret_cast<const float2*>(bp + col);
#pragma unroll
            for (int h = 0; h < 2; h++) {
                int r = rbase + mt * 16 + h * 8;
                if (r < seg_count) {
                    float v0 = cc[h * 2 + 0] + bb.x;
                    float v1 = cc[h * 2 + 1] + bb.y;
                    size_t off = (size_t)(seg_start + r) * N_TOTAL + n0 + col;
                    if (RELU_OUT) {
                        v0 = fmaxf(v0, 0.0f);
                        v1 = fmaxf(v1, 0.0f);
                        __half2 hv = __floats2half2_rn(v0, v1);
                        *reinterpret_cast<uint32_t*>(g_Y1 + off) =
                            *reinterpret_cast<uint32_t*>(&hv);
                    } else {
                        float2 o; o.x = v0; o.y = v1;
                        *reinterpret_cast<float2*>(g_Y2 + off) = o;
                    }
                }
            }
        }
    }
}

// ---------------- combine ----------------------------------------------------
__global__ void combine_kernel(float* __restrict__ out) {
    int idx = blockIdx.x * blockDim.x + threadIdx.x;
    const int vec_per_row = DM / 4;
    int t = idx / vec_per_row;
    int c = idx - t * vec_per_row;
    if (t >= T_TOKENS) return;
    int r0 = g_slot[t * 2], r1 = g_slot[t * 2 + 1];
    float g0 = g_tok_g[t * 2], g1 = g_tok_g[t * 2 + 1];
    float4 y0 = reinterpret_cast<const float4*>(g_Y2 + (size_t)r0 * DM)[c];
    float4 y1 = reinterpret_cast<const float4*>(g_Y2 + (size_t)r1 * DM)[c];
    float4 o;
    o.x = fmaf(g0, y0.x, g1 * y1.x);
    o.y = fmaf(g0, y0.y, g1 * y1.y);
    o.z = fmaf(g0, y0.z, g1 * y1.z);
    o.w = fmaf(g0, y0.w, g1 * y1.w);
    reinterpret_cast<float4*>(out)[idx] = o;
}

// ---------------- launch ------------------------------------------------------
extern "C" void kernel_launch(void* const* d_in, const int* in_sizes, int n_in,
                              void* d_out, int out_size) {
    const float* x  = (const float*)d_in[0];
    const float* Wg = (const float*)d_in[1];
    const float* bg = (const float*)d_in[2];
    const float* W1 = (const float*)d_in[3];
    const float* b1 = (const float*)d_in[4];
    const float* W2 = (const float*)d_in[5];
    const float* b2 = (const float*)d_in[6];
    float* out = (float*)d_out;

    constexpr int BUF_BYTES = (128 * 40 + 32 * 136) * 2;   // 18944
    constexpr int SMEM = 3 * BUF_BYTES;                    // 56832
    cudaFuncSetAttribute(moe_mma<DM, DF, 1>,
                         cudaFuncAttributeMaxDynamicSharedMemorySize, SMEM);
    cudaFuncSetAttribute(moe_mma<DF, DM, 0>,
                         cudaFuncAttributeMaxDynamicSharedMemorySize, SMEM);

    init_kernel<<<1, 32>>>();
    gate_kernel<<<T_TOKENS / 128, 128>>>(x, Wg, bg);
    prefix_kernel<<<1, 32>>>();
    scatter_kernel<<<NPAIRS / 256, 256>>>();
    gather_convert<<<(NPAIRS * (DM / 4)) / 256, 256>>>(x);
    convert_w<0><<<(NE * DM * DF / 4) / 256, 256>>>(W1);
    convert_w<1><<<(NE * DF * DM / 4) / 256, 256>>>(W2);

    dim3 grid1(NPAIRS / 128, DF / 128, NE);   // (64, 16, 8), dead tiles exit
    moe_mma<DM, DF, 1><<<grid1, 256, SMEM>>>(b1);

    dim3 grid2(NPAIRS / 128, DM / 128, NE);   // (64, 4, 8)
    moe_mma<DF, DM, 0><<<grid2, 256, SMEM>>>(b2);

    combine_kernel<<<(T_TOKENS * DM / 4 + 255) / 256, 256>>>(out);
}